// round 10
// baseline (speedup 1.0000x reference)
#include <cuda_runtime.h>
#include <math.h>
#include <stdint.h>

typedef unsigned long long ull;

// ---------------- constants ----------------
#define BS_     2048
#define A_      32
#define ROWS    (BS_ * A_)     // 65536
#define IN_DIM  256
#define HID     256
#define NH      4
#define HD      16
#define CV      16
#define TOPK    8
#define NACT    20
#define QKVG_N  196            // 64 q + 64 k + 64 v + 4 g
#define NEGV    (-1e10f)

#define M_NONE 0
#define M_RELU 1
#define M_QKVG 2

// ---------------- scratch (device globals; no allocation) ----------------
__device__ float g_x   [ROWS * HID];
__device__ float g_gi  [ROWS * 3 * HID];
__device__ float g_gh  [ROWS * 3 * HID];
__device__ float g_qkvg[ROWS * QKVG_N];
__device__ float g_msg [ROWS * (NH * CV)];
__device__ float g_p1  [ROWS * HID];
__device__ float g_wq  [QKVG_N * HID];
__device__ float g_bq  [QKVG_N];

// ---------------- helpers ----------------
__device__ __forceinline__ float sigmoidf_(float x) { return 1.0f / (1.0f + expf(-x)); }
__device__ __forceinline__ uint32_t f2tf32(float x) {
    uint32_t u; asm("cvt.rna.tf32.f32 %0, %1;" : "=r"(u) : "f"(x)); return u;
}
// split v into tf32 hi + tf32 lo (3xTF32 decomposition)
__device__ __forceinline__ void tfsplit(float v, uint32_t& hi, uint32_t& lo) {
    hi = f2tf32(v);
    lo = f2tf32(v - __uint_as_float(hi));
}
__device__ __forceinline__ void mma_tf32(float* c, const uint32_t* a, const uint32_t* b) {
    asm volatile(
        "mma.sync.aligned.m16n8k8.row.col.f32.tf32.tf32.f32 "
        "{%0,%1,%2,%3}, {%4,%5,%6,%7}, {%8,%9}, {%0,%1,%2,%3};"
        : "+f"(c[0]), "+f"(c[1]), "+f"(c[2]), "+f"(c[3])
        : "r"(a[0]), "r"(a[1]), "r"(a[2]), "r"(a[3]), "r"(b[0]), "r"(b[1]));
}

// ---------------- 3xTF32 mma.sync GEMM ----------------
// C[M,N] = A[M,K] @ B[N,K]^T + bias (fp32-accurate via 3-term tf32 split), fused act.
// Split-A source: k < K1 from A1 (lda1) else A2 at k-K1 (lda2). K1 % 16 == 0, K % 16 == 0.
// CTA tile 128x128, K-chunk 16, 256 threads (8 warps = 2m x 4n), warp tile 64x32.
// Smem per stage (floats): A_hi[2048] A_lo[2048] B_hi[2048] B_lo[2048] = 32KB.
// Double-buffered: 64KB dynamic smem.
#define TG_SMEM 65536

__global__ __launch_bounds__(256) void tgemm_mma3(
    const float* __restrict__ A1, const float* __restrict__ A2,
    int K1, int lda1, int lda2,
    const float* __restrict__ B, const float* __restrict__ bias,
    float* __restrict__ C, int ldc, int N, int K, int mode)
{
    extern __shared__ float smf[];

    const int tid = threadIdx.x;
    const int lane = tid & 31;
    const int wid = tid >> 5;
    const int wm = wid & 1;          // m offset wm*64
    const int wn = wid >> 1;         // n offset wn*32
    const int m0 = blockIdx.y * 128;
    const int n0 = blockIdx.x * 128;

    // staging coords (two passes r=0,1 over e = tid + r*256)
    // row = e>>2 (0..127), kq = (e&3)*4
    float acc[4][4][4];
#pragma unroll
    for (int i = 0; i < 4; i++)
#pragma unroll
        for (int j = 0; j < 4; j++)
#pragma unroll
            for (int r = 0; r < 4; r++) acc[i][j][r] = 0.f;

    const int nch = K / 16;

    // ---- stage chunk 0 ----
    {
        uint32_t* base = (uint32_t*)smf;
#pragma unroll
        for (int r = 0; r < 2; r++) {
            int e = tid + r * 256;
            int row = e >> 2;
            int kq = (e & 3) * 4;
            int kg = kq;
            const float* pA = (kg < K1) ? A1 + (size_t)(m0 + row) * lda1 + kg
                                        : A2 + (size_t)(m0 + row) * lda2 + (kg - K1);
            float4 va = *(const float4*)pA;
            float4 vb = make_float4(0.f, 0.f, 0.f, 0.f);
            if (n0 + row < N) vb = *(const float4*)(B + (size_t)(n0 + row) * K + kg);

            int mf = row >> 4, rr = row & 15, gidA = rr & 7, hi_ = rr >> 3;
            int ks = kq >> 3, chi = (kq >> 2) & 1;
            int offA = ((ks * 8 + mf) * 32 + gidA * 4) * 4 + hi_ + 2 * chi;
            int nf = row >> 3, gidB = row & 7;
            int offB = ((ks * 16 + nf) * 32 + gidB * 4) * 2 + chi;

            uint32_t h, l;
            tfsplit(va.x, h, l); base[offA + 0]  = h; base[2048 + offA + 0]  = l;
            tfsplit(va.y, h, l); base[offA + 4]  = h; base[2048 + offA + 4]  = l;
            tfsplit(va.z, h, l); base[offA + 8]  = h; base[2048 + offA + 8]  = l;
            tfsplit(va.w, h, l); base[offA + 12] = h; base[2048 + offA + 12] = l;
            tfsplit(vb.x, h, l); base[4096 + offB + 0] = h; base[6144 + offB + 0] = l;
            tfsplit(vb.y, h, l); base[4096 + offB + 2] = h; base[6144 + offB + 2] = l;
            tfsplit(vb.z, h, l); base[4096 + offB + 4] = h; base[6144 + offB + 4] = l;
            tfsplit(vb.w, h, l); base[4096 + offB + 6] = h; base[6144 + offB + 6] = l;
        }
    }
    __syncthreads();

    for (int c = 0; c < nch; c++) {
        // ---- prefetch chunk c+1 into registers ----
        float4 fA[2], fB[2];
        if (c + 1 < nch) {
#pragma unroll
            for (int r = 0; r < 2; r++) {
                int e = tid + r * 256;
                int row = e >> 2;
                int kq = (e & 3) * 4;
                int kg = (c + 1) * 16 + kq;
                const float* pA = (kg < K1) ? A1 + (size_t)(m0 + row) * lda1 + kg
                                            : A2 + (size_t)(m0 + row) * lda2 + (kg - K1);
                fA[r] = *(const float4*)pA;
                fB[r] = make_float4(0.f, 0.f, 0.f, 0.f);
                if (n0 + row < N) fB[r] = *(const float4*)(B + (size_t)(n0 + row) * K + kg);
            }
        }

        // ---- compute chunk c ----
        const float* sAh = smf + (c & 1) * 8192;
        const float* sAl = sAh + 2048;
        const float* sBh = sAh + 4096;
        const float* sBl = sAh + 6144;
#pragma unroll
        for (int ks = 0; ks < 2; ks++) {
            uint32_t bh[4][2], bl[4][2];
#pragma unroll
            for (int j = 0; j < 4; j++) {
                float2 vh = *(const float2*)(sBh + ((ks * 16 + wn * 4 + j) * 32 + lane) * 2);
                float2 vl = *(const float2*)(sBl + ((ks * 16 + wn * 4 + j) * 32 + lane) * 2);
                bh[j][0] = __float_as_uint(vh.x); bh[j][1] = __float_as_uint(vh.y);
                bl[j][0] = __float_as_uint(vl.x); bl[j][1] = __float_as_uint(vl.y);
            }
#pragma unroll
            for (int i = 0; i < 4; i++) {
                uint32_t ah[4], al[4];
                float4 vh = *(const float4*)(sAh + ((ks * 8 + wm * 4 + i) * 32 + lane) * 4);
                float4 vl = *(const float4*)(sAl + ((ks * 8 + wm * 4 + i) * 32 + lane) * 4);
                ah[0] = __float_as_uint(vh.x); ah[1] = __float_as_uint(vh.y);
                ah[2] = __float_as_uint(vh.z); ah[3] = __float_as_uint(vh.w);
                al[0] = __float_as_uint(vl.x); al[1] = __float_as_uint(vl.y);
                al[2] = __float_as_uint(vl.z); al[3] = __float_as_uint(vl.w);
#pragma unroll
                for (int j = 0; j < 4; j++) {
                    mma_tf32(acc[i][j], al, bh[j]);   // lo*hi
                    mma_tf32(acc[i][j], ah, bl[j]);   // hi*lo
                    mma_tf32(acc[i][j], ah, bh[j]);   // hi*hi
                }
            }
        }

        // ---- split + scatter-store chunk c+1 ----
        if (c + 1 < nch) {
            uint32_t* base = (uint32_t*)(smf + ((c + 1) & 1) * 8192);
#pragma unroll
            for (int r = 0; r < 2; r++) {
                int e = tid + r * 256;
                int row = e >> 2;
                int kq = (e & 3) * 4;
                int mf = row >> 4, rr = row & 15, gidA = rr & 7, hi_ = rr >> 3;
                int ks = kq >> 3, chi = (kq >> 2) & 1;
                int offA = ((ks * 8 + mf) * 32 + gidA * 4) * 4 + hi_ + 2 * chi;
                int nf = row >> 3, gidB = row & 7;
                int offB = ((ks * 16 + nf) * 32 + gidB * 4) * 2 + chi;
                uint32_t h, l;
                tfsplit(fA[r].x, h, l); base[offA + 0]  = h; base[2048 + offA + 0]  = l;
                tfsplit(fA[r].y, h, l); base[offA + 4]  = h; base[2048 + offA + 4]  = l;
                tfsplit(fA[r].z, h, l); base[offA + 8]  = h; base[2048 + offA + 8]  = l;
                tfsplit(fA[r].w, h, l); base[offA + 12] = h; base[2048 + offA + 12] = l;
                tfsplit(fB[r].x, h, l); base[4096 + offB + 0] = h; base[6144 + offB + 0] = l;
                tfsplit(fB[r].y, h, l); base[4096 + offB + 2] = h; base[6144 + offB + 2] = l;
                tfsplit(fB[r].z, h, l); base[4096 + offB + 4] = h; base[6144 + offB + 4] = l;
                tfsplit(fB[r].w, h, l); base[4096 + offB + 6] = h; base[6144 + offB + 6] = l;
            }
        }
        __syncthreads();
    }

    // ---- epilogue ----
    const int gid = lane >> 2;
    const int tig = lane & 3;
#pragma unroll
    for (int i = 0; i < 4; i++) {
        const int row0 = m0 + wm * 64 + i * 16 + gid;
#pragma unroll
        for (int j = 0; j < 4; j++) {
            const int col = n0 + wn * 32 + j * 8 + tig * 2;
            if (col < N) {
                float b0 = bias[col], b1 = bias[col + 1];
                float v0 = acc[i][j][0] + b0, v1 = acc[i][j][1] + b1;
                float v2 = acc[i][j][2] + b0, v3 = acc[i][j][3] + b1;
                if (mode == M_RELU) {
                    v0 = fmaxf(v0, 0.f); v1 = fmaxf(v1, 0.f);
                    v2 = fmaxf(v2, 0.f); v3 = fmaxf(v3, 0.f);
                } else if (mode == M_QKVG && col >= 192) {
                    v0 = sigmoidf_(v0); v1 = sigmoidf_(v1);
                    v2 = sigmoidf_(v2); v3 = sigmoidf_(v3);
                }
                *(float2*)(C + (size_t)row0 * ldc + col)       = make_float2(v0, v1);
                *(float2*)(C + (size_t)(row0 + 8) * ldc + col) = make_float2(v2, v3);
            }
        }
    }
}

// ---------------- SIMT f32x2 GEMM (p2, N=20) ----------------
__device__ __forceinline__ ull pk2(float x) {
    ull r; asm("mov.b64 %0, {%1, %1};" : "=l"(r) : "f"(x)); return r;
}
__device__ __forceinline__ ull pk(float x, float y) {
    ull r; asm("mov.b64 %0, {%1, %2};" : "=l"(r) : "f"(x), "f"(y)); return r;
}
__device__ __forceinline__ void fma2(ull& d, ull a, ull b) {
    asm("fma.rn.f32x2 %0, %1, %2, %0;" : "+l"(d) : "l"(a), "l"(b));
}
__device__ __forceinline__ void unpk(ull v, float& x, float& y) {
    asm("mov.b64 {%0, %1}, %2;" : "=f"(x), "=f"(y) : "l"(v));
}

#define BM 128
#define BK 16
template<int BN>
__global__ __launch_bounds__(256, 2) void gemm8x8(
    const float* __restrict__ A1, const float* __restrict__ B, const float* __restrict__ bias,
    float* __restrict__ C, int ldc, int N, int K, int lda)
{
    constexpr int TN  = BN / 16;
    constexpr int PAD = 4;
    __shared__ __align__(16) float As[BK][BM + PAD];
    __shared__ __align__(16) float Bs[BK][BN + PAD];

    const int tid = threadIdx.x;
    const int m0 = blockIdx.y * BM;
    const int n0 = blockIdx.x * BN;
    const int tx = tid & 15;
    const int ty = tid >> 4;

    ull acc[8][TN / 2];
#pragma unroll
    for (int i = 0; i < 8; i++)
#pragma unroll
        for (int p = 0; p < TN / 2; p++) acc[i][p] = 0ull;

    for (int k0 = 0; k0 < K; k0 += BK) {
#pragma unroll
        for (int r = 0; r < 2; r++) {
            int e = tid + r * 256;
            int row = e >> 2;
            int kq = (e & 3) * 4;
            float4 v = *(const float4*)(A1 + (size_t)(m0 + row) * lda + k0 + kq);
            As[kq + 0][row] = v.x; As[kq + 1][row] = v.y;
            As[kq + 2][row] = v.z; As[kq + 3][row] = v.w;
        }
#pragma unroll
        for (int r = 0; r < BN / 64; r++) {
            int e = tid + r * 256;
            int col = e >> 2;
            int kq = (e & 3) * 4;
            float4 v = make_float4(0.f, 0.f, 0.f, 0.f);
            if (n0 + col < N) v = *(const float4*)(B + (size_t)(n0 + col) * K + k0 + kq);
            Bs[kq + 0][col] = v.x; Bs[kq + 1][col] = v.y;
            Bs[kq + 2][col] = v.z; Bs[kq + 3][col] = v.w;
        }
        __syncthreads();

#pragma unroll
        for (int kk = 0; kk < BK; kk++) {
            float4 a0 = *(const float4*)&As[kk][ty * 8];
            float4 a1 = *(const float4*)&As[kk][ty * 8 + 4];
            float am[8] = {a0.x, a0.y, a0.z, a0.w, a1.x, a1.y, a1.z, a1.w};
            float bn_[TN];
#pragma unroll
            for (int q = 0; q < TN / 4; q++) {
                float4 b = *(const float4*)&Bs[kk][tx * TN + q * 4];
                bn_[q * 4 + 0] = b.x; bn_[q * 4 + 1] = b.y;
                bn_[q * 4 + 2] = b.z; bn_[q * 4 + 3] = b.w;
            }
            ull bp[TN / 2];
#pragma unroll
            for (int p = 0; p < TN / 2; p++) bp[p] = pk(bn_[2 * p], bn_[2 * p + 1]);
#pragma unroll
            for (int i = 0; i < 8; i++) {
                ull aa = pk2(am[i]);
#pragma unroll
                for (int p = 0; p < TN / 2; p++) fma2(acc[i][p], aa, bp[p]);
            }
        }
        __syncthreads();
    }

#pragma unroll
    for (int i = 0; i < 8; i++) {
        int row = m0 + ty * 8 + i;
        float vals[TN];
#pragma unroll
        for (int p = 0; p < TN / 2; p++) unpk(acc[i][p], vals[2 * p], vals[2 * p + 1]);
#pragma unroll
        for (int j = 0; j < TN; j++) {
            int col = n0 + tx * TN + j;
            if (col < N) C[(size_t)row * ldc + col] = vals[j] + bias[col];
        }
    }
}

// ---------------- pack q/k/v/g ----------------
__global__ void pack_qkvg(const float* __restrict__ qw, const float* __restrict__ qb,
                          const float* __restrict__ kw, const float* __restrict__ kb,
                          const float* __restrict__ vw, const float* __restrict__ vb,
                          const float* __restrict__ gw, const float* __restrict__ gb)
{
    int i = blockIdx.x * blockDim.x + threadIdx.x;
    const int total = QKVG_N * HID;
    if (i < total) {
        int row = i / HID, c = i - row * HID;
        float v;
        if      (row < 64)  v = qw[row * HID + c];
        else if (row < 128) v = kw[(row - 64) * HID + c];
        else if (row < 192) v = vw[(row - 128) * HID + c];
        else                v = gw[(row - 192) * HID + c];
        g_wq[i] = v;
    }
    if (i < QKVG_N) {
        float b;
        if      (i < 64)  b = qb[i];
        else if (i < 128) b = kb[i - 64];
        else if (i < 192) b = vb[i - 128];
        else              b = gb[i - 192];
        g_bq[i] = b;
    }
}

// ---------------- GRU gate fusion ----------------
__global__ void gru_gates(const float* __restrict__ gi, const float* __restrict__ gh,
                          const float* __restrict__ hin, float* __restrict__ hout)
{
    int i4 = blockIdx.x * blockDim.x + threadIdx.x;
    if (i4 >= ROWS * (HID / 4)) return;
    int row = i4 >> 6;
    int c   = (i4 & 63) << 2;
    const float* gib = gi + (size_t)row * 768 + c;
    const float* ghb = gh + (size_t)row * 768 + c;
    float4 gir = *(const float4*)(gib);
    float4 giz = *(const float4*)(gib + 256);
    float4 gin = *(const float4*)(gib + 512);
    float4 ghr = *(const float4*)(ghb);
    float4 ghz = *(const float4*)(ghb + 256);
    float4 ghn = *(const float4*)(ghb + 512);
    float4 h0  = *(const float4*)(hin + (size_t)row * HID + c);
    float4 o;
    {
        float r = sigmoidf_(gir.x + ghr.x);
        float z = sigmoidf_(giz.x + ghz.x);
        float n = tanhf(gin.x + r * ghn.x);
        o.x = (1.f - z) * n + z * h0.x;
    }
    {
        float r = sigmoidf_(gir.y + ghr.y);
        float z = sigmoidf_(giz.y + ghz.y);
        float n = tanhf(gin.y + r * ghn.y);
        o.y = (1.f - z) * n + z * h0.y;
    }
    {
        float r = sigmoidf_(gir.z + ghr.z);
        float z = sigmoidf_(giz.z + ghz.z);
        float n = tanhf(gin.z + r * ghn.z);
        o.z = (1.f - z) * n + z * h0.z;
    }
    {
        float r = sigmoidf_(gir.w + ghr.w);
        float z = sigmoidf_(giz.w + ghz.w);
        float n = tanhf(gin.w + r * ghn.w);
        o.w = (1.f - z) * n + z * h0.w;
    }
    *(float4*)(hout + (size_t)row * HID + c) = o;
}

// ---------------- per-batch sparse attention ----------------
__global__ __launch_bounds__(128) void attention_kernel(const float* __restrict__ qkvg,
                                                        float* __restrict__ msg)
{
    __shared__ float q_s[A_][64];
    __shared__ float k_s[A_][64];
    __shared__ float v_s[A_][64];
    __shared__ float g_s[A_][NH];

    const int b = blockIdx.x;
    const int tid = threadIdx.x;
    const float* base = qkvg + (size_t)b * A_ * QKVG_N;

    for (int idx = tid; idx < A_ * QKVG_N; idx += 128) {
        int r = idx / QKVG_N, c = idx - r * QKVG_N;
        float v = base[(size_t)r * QKVG_N + c];
        if      (c < 64)  q_s[r][c] = v;
        else if (c < 128) k_s[r][c - 64] = v;
        else if (c < 192) v_s[r][c - 128] = v;
        else              g_s[r][c - 192] = v;
    }
    __syncthreads();

    const int qa = tid >> 2;
    const int hh = tid & 3;
    const int hb = hh * HD;

    float qv[HD];
#pragma unroll
    for (int d = 0; d < HD; d++) qv[d] = q_s[qa][hb + d];

    float sc[A_];
#pragma unroll
    for (int ka = 0; ka < A_; ka++) {
        float s = 0.f;
#pragma unroll
        for (int d = 0; d < HD; d++) s += qv[d] * k_s[ka][hb + d];
        sc[ka] = (ka == qa) ? NEGV : s * 0.25f;
    }

    unsigned sel = 0;
    float maxv = NEGV;
    for (int it = 0; it < TOPK; it++) {
        float best = -INFINITY; int bi = 0;
#pragma unroll
        for (int ka = 0; ka < A_; ka++) {
            bool free_ = !((sel >> ka) & 1u);
            if (free_ && sc[ka] > best) { best = sc[ka]; bi = ka; }
        }
        sel |= (1u << bi);
        if (it == 0) maxv = best;
    }

    float sum = 0.f;
#pragma unroll
    for (int ka = 0; ka < A_; ka++) {
        float e = ((sel >> ka) & 1u) ? expf(sc[ka] - maxv) : 0.f;
        sc[ka] = e;
        sum += e;
    }
    float inv = 1.f / sum;

    float m[CV];
#pragma unroll
    for (int d = 0; d < CV; d++) m[d] = 0.f;
#pragma unroll
    for (int ka = 0; ka < A_; ka++) {
        float w = sc[ka];
#pragma unroll
        for (int d = 0; d < CV; d++) m[d] += w * v_s[ka][hb + d];
    }

    float gate = g_s[qa][hh];
    float* out = msg + ((size_t)(b * A_ + qa)) * (NH * CV) + hb;
#pragma unroll
    for (int d = 0; d < CV; d++) out[d] = m[d] * inv * gate;
}

// ---------------- launch ----------------
extern "C" void kernel_launch(void* const* d_in, const int* in_sizes, int n_in,
                              void* d_out, int out_size)
{
    const float* inputs = (const float*)d_in[0];
    const float* hidden = (const float*)d_in[1];
    const float* fc1_w  = (const float*)d_in[2];
    const float* fc1_b  = (const float*)d_in[3];
    const float* w_ih   = (const float*)d_in[4];
    const float* w_hh   = (const float*)d_in[5];
    const float* b_ih   = (const float*)d_in[6];
    const float* b_hh   = (const float*)d_in[7];
    const float* q_w    = (const float*)d_in[8];
    const float* q_b    = (const float*)d_in[9];
    const float* k_w    = (const float*)d_in[10];
    const float* k_b    = (const float*)d_in[11];
    const float* v_w    = (const float*)d_in[12];
    const float* v_b    = (const float*)d_in[13];
    const float* g_w    = (const float*)d_in[14];
    const float* g_b    = (const float*)d_in[15];
    const float* p1_w   = (const float*)d_in[16];
    const float* p1_b   = (const float*)d_in[17];
    const float* p2_w   = (const float*)d_in[18];
    const float* p2_b   = (const float*)d_in[19];

    float* out    = (float*)d_out;
    float* logits = out;                       // [65536, 20]
    float* hout   = out + (size_t)ROWS * NACT; // [65536, 256]

    float *x, *gi, *gh, *qkvg, *msg, *p1, *wq, *bq;
    cudaGetSymbolAddress((void**)&x,    g_x);
    cudaGetSymbolAddress((void**)&gi,   g_gi);
    cudaGetSymbolAddress((void**)&gh,   g_gh);
    cudaGetSymbolAddress((void**)&qkvg, g_qkvg);
    cudaGetSymbolAddress((void**)&msg,  g_msg);
    cudaGetSymbolAddress((void**)&p1,   g_p1);
    cudaGetSymbolAddress((void**)&wq,   g_wq);
    cudaGetSymbolAddress((void**)&bq,   g_bq);

    static bool attr_done = false;
    if (!attr_done) {
        cudaFuncSetAttribute(tgemm_mma3, cudaFuncAttributeMaxDynamicSharedMemorySize, TG_SMEM);
        attr_done = true;
    }

    const int MYT = ROWS / 128;   // 512

    pack_qkvg<<<(QKVG_N * HID + 255) / 256, 256>>>(q_w, q_b, k_w, k_b, v_w, v_b, g_w, g_b);

    // x = relu(inputs @ fc1_w^T + fc1_b)
    tgemm_mma3<<<dim3(HID / 128, MYT), 256, TG_SMEM>>>(
        inputs, inputs, IN_DIM, IN_DIM, IN_DIM, fc1_w, fc1_b, x, HID, HID, IN_DIM, M_RELU);
    // gi = x @ w_ih^T + b_ih ; gh = hidden @ w_hh^T + b_hh
    tgemm_mma3<<<dim3(3 * HID / 128, MYT), 256, TG_SMEM>>>(
        x, x, HID, HID, HID, w_ih, b_ih, gi, 3 * HID, 3 * HID, HID, M_NONE);
    tgemm_mma3<<<dim3(3 * HID / 128, MYT), 256, TG_SMEM>>>(
        hidden, hidden, HID, HID, HID, w_hh, b_hh, gh, 3 * HID, 3 * HID, HID, M_NONE);
    // h
    gru_gates<<<(ROWS * (HID / 4) + 255) / 256, 256>>>(gi, gh, hidden, hout);
    // q|k|v|sig(g)
    tgemm_mma3<<<dim3((QKVG_N + 127) / 128, MYT), 256, TG_SMEM>>>(
        hout, hout, HID, HID, HID, wq, bq, qkvg, QKVG_N, QKVG_N, HID, M_QKVG);
    // sparse attention -> gated messages
    attention_kernel<<<BS_, 128>>>(qkvg, msg);
    // p1 = relu([h | msg] @ p1_w^T + p1_b)   (split-A, K=320)
    tgemm_mma3<<<dim3(HID / 128, MYT), 256, TG_SMEM>>>(
        hout, msg, HID, HID, NH * CV, p1_w, p1_b, p1, HID, HID, HID + NH * CV, M_RELU);
    // logits = p1 @ p2_w^T + p2_b  (SIMT fp32, N=20)
    gemm8x8<64><<<dim3(1, ROWS / BM), 256>>>(p1, p2_w, p2_b, logits, NACT, NACT, HID, HID);
}

// round 11
// speedup vs baseline: 1.1829x; 1.1829x over previous
#include <cuda_runtime.h>
#include <math.h>
#include <stdint.h>

typedef unsigned long long ull;

// ---------------- constants ----------------
#define BS_     2048
#define A_      32
#define ROWS    (BS_ * A_)     // 65536
#define IN_DIM  256
#define HID     256
#define NH      4
#define HD      16
#define CV      16
#define TOPK    8
#define NACT    20
#define QKVG_N  196            // 64 q + 64 k + 64 v + 4 g
#define NEGV    (-1e10f)

#define M_NONE 0
#define M_RELU 1
#define M_QKVG 2

// ---------------- scratch (device globals; no allocation) ----------------
__device__ float g_x   [ROWS * HID];
__device__ float g_gi  [ROWS * 3 * HID];
__device__ float g_gh  [ROWS * 3 * HID];
__device__ float g_qkvg[ROWS * QKVG_N];
__device__ float g_msg [ROWS * (NH * CV)];
__device__ float g_p1  [ROWS * HID];
__device__ float g_wq  [QKVG_N * HID];
__device__ float g_bq  [QKVG_N];

// ---------------- helpers ----------------
__device__ __forceinline__ float sigmoidf_(float x) { return 1.0f / (1.0f + expf(-x)); }
__device__ __forceinline__ uint32_t f2tf32(float x) {
    uint32_t u; asm("cvt.rna.tf32.f32 %0, %1;" : "=r"(u) : "f"(x)); return u;
}
// split v into tf32 hi + tf32 lo (3xTF32 decomposition)
__device__ __forceinline__ void tfsplit(float v, uint32_t& hi, uint32_t& lo) {
    hi = f2tf32(v);
    lo = f2tf32(v - __uint_as_float(hi));
}
__device__ __forceinline__ void mma_tf32(float* c, const uint32_t* a, const uint32_t* b) {
    asm volatile(
        "mma.sync.aligned.m16n8k8.row.col.f32.tf32.tf32.f32 "
        "{%0,%1,%2,%3}, {%4,%5,%6,%7}, {%8,%9}, {%0,%1,%2,%3};"
        : "+f"(c[0]), "+f"(c[1]), "+f"(c[2]), "+f"(c[3])
        : "r"(a[0]), "r"(a[1]), "r"(a[2]), "r"(a[3]), "r"(b[0]), "r"(b[1]));
}

// ---------------- 3xTF32 mma.sync GEMM ----------------
// C[M,N] = A[M,K] @ B[N,K]^T + bias (fp32-accurate via 3-term tf32 split), fused act.
// Split-A source: k < K1 from A1 (lda1) else A2 at k-K1 (lda2). K1 % 16 == 0, K % 16 == 0.
// CTA tile 128x128, K-chunk 16, 256 threads (8 warps = 2m x 4n), warp tile 64x32.
// Smem per stage (floats): A_hi[2048] A_lo[2048] B_hi[2048] B_lo[2048] = 32KB.
// Double-buffered: 64KB dynamic smem. __launch_bounds__(256,2) caps regs at 128
// so TWO CTAs co-reside per SM and staging overlaps MMA across CTAs.
#define TG_SMEM 65536

__global__ __launch_bounds__(256, 2) void tgemm_mma3(
    const float* __restrict__ A1, const float* __restrict__ A2,
    int K1, int lda1, int lda2,
    const float* __restrict__ B, const float* __restrict__ bias,
    float* __restrict__ C, int ldc, int N, int K, int mode)
{
    extern __shared__ float smf[];

    const int tid = threadIdx.x;
    const int lane = tid & 31;
    const int wid = tid >> 5;
    const int wm = wid & 1;          // m offset wm*64
    const int wn = wid >> 1;         // n offset wn*32
    const int m0 = blockIdx.y * 128;
    const int n0 = blockIdx.x * 128;

    float acc[4][4][4];
#pragma unroll
    for (int i = 0; i < 4; i++)
#pragma unroll
        for (int j = 0; j < 4; j++)
#pragma unroll
            for (int r = 0; r < 4; r++) acc[i][j][r] = 0.f;

    const int nch = K / 16;

    // ---- stage chunk 0 ----
    {
        uint32_t* base = (uint32_t*)smf;
#pragma unroll
        for (int r = 0; r < 2; r++) {
            int e = tid + r * 256;
            int row = e >> 2;
            int kq = (e & 3) * 4;
            int kg = kq;
            const float* pA = (kg < K1) ? A1 + (size_t)(m0 + row) * lda1 + kg
                                        : A2 + (size_t)(m0 + row) * lda2 + (kg - K1);
            float4 va = *(const float4*)pA;
            float4 vb = make_float4(0.f, 0.f, 0.f, 0.f);
            if (n0 + row < N) vb = *(const float4*)(B + (size_t)(n0 + row) * K + kg);

            int mf = row >> 4, rr = row & 15, gidA = rr & 7, hi_ = rr >> 3;
            int ks = kq >> 3, chi = (kq >> 2) & 1;
            int offA = ((ks * 8 + mf) * 32 + gidA * 4) * 4 + hi_ + 2 * chi;
            int nf = row >> 3, gidB = row & 7;
            int offB = ((ks * 16 + nf) * 32 + gidB * 4) * 2 + chi;

            uint32_t h, l;
            tfsplit(va.x, h, l); base[offA + 0]  = h; base[2048 + offA + 0]  = l;
            tfsplit(va.y, h, l); base[offA + 4]  = h; base[2048 + offA + 4]  = l;
            tfsplit(va.z, h, l); base[offA + 8]  = h; base[2048 + offA + 8]  = l;
            tfsplit(va.w, h, l); base[offA + 12] = h; base[2048 + offA + 12] = l;
            tfsplit(vb.x, h, l); base[4096 + offB + 0] = h; base[6144 + offB + 0] = l;
            tfsplit(vb.y, h, l); base[4096 + offB + 2] = h; base[6144 + offB + 2] = l;
            tfsplit(vb.z, h, l); base[4096 + offB + 4] = h; base[6144 + offB + 4] = l;
            tfsplit(vb.w, h, l); base[4096 + offB + 6] = h; base[6144 + offB + 6] = l;
        }
    }
    __syncthreads();

    for (int c = 0; c < nch; c++) {
        // ---- prefetch chunk c+1 into registers ----
        float4 fA[2], fB[2];
        if (c + 1 < nch) {
#pragma unroll
            for (int r = 0; r < 2; r++) {
                int e = tid + r * 256;
                int row = e >> 2;
                int kq = (e & 3) * 4;
                int kg = (c + 1) * 16 + kq;
                const float* pA = (kg < K1) ? A1 + (size_t)(m0 + row) * lda1 + kg
                                            : A2 + (size_t)(m0 + row) * lda2 + (kg - K1);
                fA[r] = *(const float4*)pA;
                fB[r] = make_float4(0.f, 0.f, 0.f, 0.f);
                if (n0 + row < N) fB[r] = *(const float4*)(B + (size_t)(n0 + row) * K + kg);
            }
        }

        // ---- compute chunk c ----
        const float* sAh = smf + (c & 1) * 8192;
        const float* sAl = sAh + 2048;
        const float* sBh = sAh + 4096;
        const float* sBl = sAh + 6144;
#pragma unroll
        for (int ks = 0; ks < 2; ks++) {
            uint32_t bh[4][2], bl[4][2];
#pragma unroll
            for (int j = 0; j < 4; j++) {
                float2 vh = *(const float2*)(sBh + ((ks * 16 + wn * 4 + j) * 32 + lane) * 2);
                float2 vl = *(const float2*)(sBl + ((ks * 16 + wn * 4 + j) * 32 + lane) * 2);
                bh[j][0] = __float_as_uint(vh.x); bh[j][1] = __float_as_uint(vh.y);
                bl[j][0] = __float_as_uint(vl.x); bl[j][1] = __float_as_uint(vl.y);
            }
#pragma unroll
            for (int i = 0; i < 4; i++) {
                uint32_t ah[4], al[4];
                float4 vh = *(const float4*)(sAh + ((ks * 8 + wm * 4 + i) * 32 + lane) * 4);
                float4 vl = *(const float4*)(sAl + ((ks * 8 + wm * 4 + i) * 32 + lane) * 4);
                ah[0] = __float_as_uint(vh.x); ah[1] = __float_as_uint(vh.y);
                ah[2] = __float_as_uint(vh.z); ah[3] = __float_as_uint(vh.w);
                al[0] = __float_as_uint(vl.x); al[1] = __float_as_uint(vl.y);
                al[2] = __float_as_uint(vl.z); al[3] = __float_as_uint(vl.w);
#pragma unroll
                for (int j = 0; j < 4; j++) {
                    mma_tf32(acc[i][j], al, bh[j]);   // lo*hi
                    mma_tf32(acc[i][j], ah, bl[j]);   // hi*lo
                    mma_tf32(acc[i][j], ah, bh[j]);   // hi*hi
                }
            }
        }

        // ---- split + scatter-store chunk c+1 ----
        if (c + 1 < nch) {
            uint32_t* base = (uint32_t*)(smf + ((c + 1) & 1) * 8192);
#pragma unroll
            for (int r = 0; r < 2; r++) {
                int e = tid + r * 256;
                int row = e >> 2;
                int kq = (e & 3) * 4;
                int mf = row >> 4, rr = row & 15, gidA = rr & 7, hi_ = rr >> 3;
                int ks = kq >> 3, chi = (kq >> 2) & 1;
                int offA = ((ks * 8 + mf) * 32 + gidA * 4) * 4 + hi_ + 2 * chi;
                int nf = row >> 3, gidB = row & 7;
                int offB = ((ks * 16 + nf) * 32 + gidB * 4) * 2 + chi;
                uint32_t h, l;
                tfsplit(fA[r].x, h, l); base[offA + 0]  = h; base[2048 + offA + 0]  = l;
                tfsplit(fA[r].y, h, l); base[offA + 4]  = h; base[2048 + offA + 4]  = l;
                tfsplit(fA[r].z, h, l); base[offA + 8]  = h; base[2048 + offA + 8]  = l;
                tfsplit(fA[r].w, h, l); base[offA + 12] = h; base[2048 + offA + 12] = l;
                tfsplit(fB[r].x, h, l); base[4096 + offB + 0] = h; base[6144 + offB + 0] = l;
                tfsplit(fB[r].y, h, l); base[4096 + offB + 2] = h; base[6144 + offB + 2] = l;
                tfsplit(fB[r].z, h, l); base[4096 + offB + 4] = h; base[6144 + offB + 4] = l;
                tfsplit(fB[r].w, h, l); base[4096 + offB + 6] = h; base[6144 + offB + 6] = l;
            }
        }
        __syncthreads();
    }

    // ---- epilogue ----
    const int gid = lane >> 2;
    const int tig = lane & 3;
#pragma unroll
    for (int i = 0; i < 4; i++) {
        const int row0 = m0 + wm * 64 + i * 16 + gid;
#pragma unroll
        for (int j = 0; j < 4; j++) {
            const int col = n0 + wn * 32 + j * 8 + tig * 2;
            if (col < N) {
                float b0 = bias[col], b1 = bias[col + 1];
                float v0 = acc[i][j][0] + b0, v1 = acc[i][j][1] + b1;
                float v2 = acc[i][j][2] + b0, v3 = acc[i][j][3] + b1;
                if (mode == M_RELU) {
                    v0 = fmaxf(v0, 0.f); v1 = fmaxf(v1, 0.f);
                    v2 = fmaxf(v2, 0.f); v3 = fmaxf(v3, 0.f);
                } else if (mode == M_QKVG && col >= 192) {
                    v0 = sigmoidf_(v0); v1 = sigmoidf_(v1);
                    v2 = sigmoidf_(v2); v3 = sigmoidf_(v3);
                }
                *(float2*)(C + (size_t)row0 * ldc + col)       = make_float2(v0, v1);
                *(float2*)(C + (size_t)(row0 + 8) * ldc + col) = make_float2(v2, v3);
            }
        }
    }
}

// ---------------- SIMT f32x2 GEMM (p2, N=20) ----------------
__device__ __forceinline__ ull pk2(float x) {
    ull r; asm("mov.b64 %0, {%1, %1};" : "=l"(r) : "f"(x)); return r;
}
__device__ __forceinline__ ull pk(float x, float y) {
    ull r; asm("mov.b64 %0, {%1, %2};" : "=l"(r) : "f"(x), "f"(y)); return r;
}
__device__ __forceinline__ void fma2(ull& d, ull a, ull b) {
    asm("fma.rn.f32x2 %0, %1, %2, %0;" : "+l"(d) : "l"(a), "l"(b));
}
__device__ __forceinline__ void unpk(ull v, float& x, float& y) {
    asm("mov.b64 {%0, %1}, %2;" : "=f"(x), "=f"(y) : "l"(v));
}

#define BM 128
#define BK 16
template<int BN>
__global__ __launch_bounds__(256, 2) void gemm8x8(
    const float* __restrict__ A1, const float* __restrict__ B, const float* __restrict__ bias,
    float* __restrict__ C, int ldc, int N, int K, int lda)
{
    constexpr int TN  = BN / 16;
    constexpr int PAD = 4;
    __shared__ __align__(16) float As[BK][BM + PAD];
    __shared__ __align__(16) float Bs[BK][BN + PAD];

    const int tid = threadIdx.x;
    const int m0 = blockIdx.y * BM;
    const int n0 = blockIdx.x * BN;
    const int tx = tid & 15;
    const int ty = tid >> 4;

    ull acc[8][TN / 2];
#pragma unroll
    for (int i = 0; i < 8; i++)
#pragma unroll
        for (int p = 0; p < TN / 2; p++) acc[i][p] = 0ull;

    for (int k0 = 0; k0 < K; k0 += BK) {
#pragma unroll
        for (int r = 0; r < 2; r++) {
            int e = tid + r * 256;
            int row = e >> 2;
            int kq = (e & 3) * 4;
            float4 v = *(const float4*)(A1 + (size_t)(m0 + row) * lda + k0 + kq);
            As[kq + 0][row] = v.x; As[kq + 1][row] = v.y;
            As[kq + 2][row] = v.z; As[kq + 3][row] = v.w;
        }
#pragma unroll
        for (int r = 0; r < BN / 64; r++) {
            int e = tid + r * 256;
            int col = e >> 2;
            int kq = (e & 3) * 4;
            float4 v = make_float4(0.f, 0.f, 0.f, 0.f);
            if (n0 + col < N) v = *(const float4*)(B + (size_t)(n0 + col) * K + k0 + kq);
            Bs[kq + 0][col] = v.x; Bs[kq + 1][col] = v.y;
            Bs[kq + 2][col] = v.z; Bs[kq + 3][col] = v.w;
        }
        __syncthreads();

#pragma unroll
        for (int kk = 0; kk < BK; kk++) {
            float4 a0 = *(const float4*)&As[kk][ty * 8];
            float4 a1 = *(const float4*)&As[kk][ty * 8 + 4];
            float am[8] = {a0.x, a0.y, a0.z, a0.w, a1.x, a1.y, a1.z, a1.w};
            float bn_[TN];
#pragma unroll
            for (int q = 0; q < TN / 4; q++) {
                float4 b = *(const float4*)&Bs[kk][tx * TN + q * 4];
                bn_[q * 4 + 0] = b.x; bn_[q * 4 + 1] = b.y;
                bn_[q * 4 + 2] = b.z; bn_[q * 4 + 3] = b.w;
            }
            ull bp[TN / 2];
#pragma unroll
            for (int p = 0; p < TN / 2; p++) bp[p] = pk(bn_[2 * p], bn_[2 * p + 1]);
#pragma unroll
            for (int i = 0; i < 8; i++) {
                ull aa = pk2(am[i]);
#pragma unroll
                for (int p = 0; p < TN / 2; p++) fma2(acc[i][p], aa, bp[p]);
            }
        }
        __syncthreads();
    }

#pragma unroll
    for (int i = 0; i < 8; i++) {
        int row = m0 + ty * 8 + i;
        float vals[TN];
#pragma unroll
        for (int p = 0; p < TN / 2; p++) unpk(acc[i][p], vals[2 * p], vals[2 * p + 1]);
#pragma unroll
        for (int j = 0; j < TN; j++) {
            int col = n0 + tx * TN + j;
            if (col < N) C[(size_t)row * ldc + col] = vals[j] + bias[col];
        }
    }
}

// ---------------- pack q/k/v/g ----------------
__global__ void pack_qkvg(const float* __restrict__ qw, const float* __restrict__ qb,
                          const float* __restrict__ kw, const float* __restrict__ kb,
                          const float* __restrict__ vw, const float* __restrict__ vb,
                          const float* __restrict__ gw, const float* __restrict__ gb)
{
    int i = blockIdx.x * blockDim.x + threadIdx.x;
    const int total = QKVG_N * HID;
    if (i < total) {
        int row = i / HID, c = i - row * HID;
        float v;
        if      (row < 64)  v = qw[row * HID + c];
        else if (row < 128) v = kw[(row - 64) * HID + c];
        else if (row < 192) v = vw[(row - 128) * HID + c];
        else                v = gw[(row - 192) * HID + c];
        g_wq[i] = v;
    }
    if (i < QKVG_N) {
        float b;
        if      (i < 64)  b = qb[i];
        else if (i < 128) b = kb[i - 64];
        else if (i < 192) b = vb[i - 128];
        else              b = gb[i - 192];
        g_bq[i] = b;
    }
}

// ---------------- GRU gate fusion ----------------
__global__ void gru_gates(const float* __restrict__ gi, const float* __restrict__ gh,
                          const float* __restrict__ hin, float* __restrict__ hout)
{
    int i4 = blockIdx.x * blockDim.x + threadIdx.x;
    if (i4 >= ROWS * (HID / 4)) return;
    int row = i4 >> 6;
    int c   = (i4 & 63) << 2;
    const float* gib = gi + (size_t)row * 768 + c;
    const float* ghb = gh + (size_t)row * 768 + c;
    float4 gir = *(const float4*)(gib);
    float4 giz = *(const float4*)(gib + 256);
    float4 gin = *(const float4*)(gib + 512);
    float4 ghr = *(const float4*)(ghb);
    float4 ghz = *(const float4*)(ghb + 256);
    float4 ghn = *(const float4*)(ghb + 512);
    float4 h0  = *(const float4*)(hin + (size_t)row * HID + c);
    float4 o;
    {
        float r = sigmoidf_(gir.x + ghr.x);
        float z = sigmoidf_(giz.x + ghz.x);
        float n = tanhf(gin.x + r * ghn.x);
        o.x = (1.f - z) * n + z * h0.x;
    }
    {
        float r = sigmoidf_(gir.y + ghr.y);
        float z = sigmoidf_(giz.y + ghz.y);
        float n = tanhf(gin.y + r * ghn.y);
        o.y = (1.f - z) * n + z * h0.y;
    }
    {
        float r = sigmoidf_(gir.z + ghr.z);
        float z = sigmoidf_(giz.z + ghz.z);
        float n = tanhf(gin.z + r * ghn.z);
        o.z = (1.f - z) * n + z * h0.z;
    }
    {
        float r = sigmoidf_(gir.w + ghr.w);
        float z = sigmoidf_(giz.w + ghz.w);
        float n = tanhf(gin.w + r * ghn.w);
        o.w = (1.f - z) * n + z * h0.w;
    }
    *(float4*)(hout + (size_t)row * HID + c) = o;
}

// ---------------- per-batch sparse attention ----------------
__global__ __launch_bounds__(128) void attention_kernel(const float* __restrict__ qkvg,
                                                        float* __restrict__ msg)
{
    __shared__ float q_s[A_][64];
    __shared__ float k_s[A_][64];
    __shared__ float v_s[A_][64];
    __shared__ float g_s[A_][NH];

    const int b = blockIdx.x;
    const int tid = threadIdx.x;
    const float* base = qkvg + (size_t)b * A_ * QKVG_N;

    for (int idx = tid; idx < A_ * QKVG_N; idx += 128) {
        int r = idx / QKVG_N, c = idx - r * QKVG_N;
        float v = base[(size_t)r * QKVG_N + c];
        if      (c < 64)  q_s[r][c] = v;
        else if (c < 128) k_s[r][c - 64] = v;
        else if (c < 192) v_s[r][c - 128] = v;
        else              g_s[r][c - 192] = v;
    }
    __syncthreads();

    const int qa = tid >> 2;
    const int hh = tid & 3;
    const int hb = hh * HD;

    float qv[HD];
#pragma unroll
    for (int d = 0; d < HD; d++) qv[d] = q_s[qa][hb + d];

    float sc[A_];
#pragma unroll
    for (int ka = 0; ka < A_; ka++) {
        float s = 0.f;
#pragma unroll
        for (int d = 0; d < HD; d++) s += qv[d] * k_s[ka][hb + d];
        sc[ka] = (ka == qa) ? NEGV : s * 0.25f;
    }

    unsigned sel = 0;
    float maxv = NEGV;
    for (int it = 0; it < TOPK; it++) {
        float best = -INFINITY; int bi = 0;
#pragma unroll
        for (int ka = 0; ka < A_; ka++) {
            bool free_ = !((sel >> ka) & 1u);
            if (free_ && sc[ka] > best) { best = sc[ka]; bi = ka; }
        }
        sel |= (1u << bi);
        if (it == 0) maxv = best;
    }

    float sum = 0.f;
#pragma unroll
    for (int ka = 0; ka < A_; ka++) {
        float e = ((sel >> ka) & 1u) ? expf(sc[ka] - maxv) : 0.f;
        sc[ka] = e;
        sum += e;
    }
    float inv = 1.f / sum;

    float m[CV];
#pragma unroll
    for (int d = 0; d < CV; d++) m[d] = 0.f;
#pragma unroll
    for (int ka = 0; ka < A_; ka++) {
        float w = sc[ka];
#pragma unroll
        for (int d = 0; d < CV; d++) m[d] += w * v_s[ka][hb + d];
    }

    float gate = g_s[qa][hh];
    float* out = msg + ((size_t)(b * A_ + qa)) * (NH * CV) + hb;
#pragma unroll
    for (int d = 0; d < CV; d++) out[d] = m[d] * inv * gate;
}

// ---------------- launch ----------------
extern "C" void kernel_launch(void* const* d_in, const int* in_sizes, int n_in,
                              void* d_out, int out_size)
{
    const float* inputs = (const float*)d_in[0];
    const float* hidden = (const float*)d_in[1];
    const float* fc1_w  = (const float*)d_in[2];
    const float* fc1_b  = (const float*)d_in[3];
    const float* w_ih   = (const float*)d_in[4];
    const float* w_hh   = (const float*)d_in[5];
    const float* b_ih   = (const float*)d_in[6];
    const float* b_hh   = (const float*)d_in[7];
    const float* q_w    = (const float*)d_in[8];
    const float* q_b    = (const float*)d_in[9];
    const float* k_w    = (const float*)d_in[10];
    const float* k_b    = (const float*)d_in[11];
    const float* v_w    = (const float*)d_in[12];
    const float* v_b    = (const float*)d_in[13];
    const float* g_w    = (const float*)d_in[14];
    const float* g_b    = (const float*)d_in[15];
    const float* p1_w   = (const float*)d_in[16];
    const float* p1_b   = (const float*)d_in[17];
    const float* p2_w   = (const float*)d_in[18];
    const float* p2_b   = (const float*)d_in[19];

    float* out    = (float*)d_out;
    float* logits = out;                       // [65536, 20]
    float* hout   = out + (size_t)ROWS * NACT; // [65536, 256]

    float *x, *gi, *gh, *qkvg, *msg, *p1, *wq, *bq;
    cudaGetSymbolAddress((void**)&x,    g_x);
    cudaGetSymbolAddress((void**)&gi,   g_gi);
    cudaGetSymbolAddress((void**)&gh,   g_gh);
    cudaGetSymbolAddress((void**)&qkvg, g_qkvg);
    cudaGetSymbolAddress((void**)&msg,  g_msg);
    cudaGetSymbolAddress((void**)&p1,   g_p1);
    cudaGetSymbolAddress((void**)&wq,   g_wq);
    cudaGetSymbolAddress((void**)&bq,   g_bq);

    static bool attr_done = false;
    if (!attr_done) {
        cudaFuncSetAttribute(tgemm_mma3, cudaFuncAttributeMaxDynamicSharedMemorySize, TG_SMEM);
        attr_done = true;
    }

    const int MYT = ROWS / 128;   // 512

    pack_qkvg<<<(QKVG_N * HID + 255) / 256, 256>>>(q_w, q_b, k_w, k_b, v_w, v_b, g_w, g_b);

    // x = relu(inputs @ fc1_w^T + fc1_b)
    tgemm_mma3<<<dim3(HID / 128, MYT), 256, TG_SMEM>>>(
        inputs, inputs, IN_DIM, IN_DIM, IN_DIM, fc1_w, fc1_b, x, HID, HID, IN_DIM, M_RELU);
    // gi = x @ w_ih^T + b_ih ; gh = hidden @ w_hh^T + b_hh
    tgemm_mma3<<<dim3(3 * HID / 128, MYT), 256, TG_SMEM>>>(
        x, x, HID, HID, HID, w_ih, b_ih, gi, 3 * HID, 3 * HID, HID, M_NONE);
    tgemm_mma3<<<dim3(3 * HID / 128, MYT), 256, TG_SMEM>>>(
        hidden, hidden, HID, HID, HID, w_hh, b_hh, gh, 3 * HID, 3 * HID, HID, M_NONE);
    // h
    gru_gates<<<(ROWS * (HID / 4) + 255) / 256, 256>>>(gi, gh, hidden, hout);
    // q|k|v|sig(g)
    tgemm_mma3<<<dim3((QKVG_N + 127) / 128, MYT), 256, TG_SMEM>>>(
        hout, hout, HID, HID, HID, wq, bq, qkvg, QKVG_N, QKVG_N, HID, M_QKVG);
    // sparse attention -> gated messages
    attention_kernel<<<BS_, 128>>>(qkvg, msg);
    // p1 = relu([h | msg] @ p1_w^T + p1_b)   (split-A, K=320)
    tgemm_mma3<<<dim3(HID / 128, MYT), 256, TG_SMEM>>>(
        hout, msg, HID, HID, NH * CV, p1_w, p1_b, p1, HID, HID, HID + NH * CV, M_RELU);
    // logits = p1 @ p2_w^T + p2_b  (SIMT fp32, N=20)
    gemm8x8<64><<<dim3(1, ROWS / BM), 256>>>(p1, p2_w, p2_b, logits, NACT, NACT, HID, HID);
}

// round 12
// speedup vs baseline: 2.0315x; 1.7174x over previous
#include <cuda_runtime.h>
#include <cuda_fp16.h>
#include <math.h>
#include <stdint.h>

typedef unsigned long long ull;

// ---------------- constants ----------------
#define BS_     2048
#define A_      32
#define ROWS    (BS_ * A_)     // 65536
#define IN_DIM  256
#define HID     256
#define NH      4
#define HD      16
#define CV      16
#define TOPK    8
#define NACT    20
#define QKVG_N  196            // 64 q + 64 k + 64 v + 4 g
#define NEGV    (-1e10f)

#define M_NONE 0
#define M_RELU 1
#define M_QKVG 2

// ---------------- scratch (device globals; no allocation) ----------------
__device__ float g_x   [ROWS * HID];
__device__ float g_gi  [ROWS * 3 * HID];
__device__ float g_gh  [ROWS * 3 * HID];
__device__ float g_qkvg[ROWS * QKVG_N];
__device__ float g_msg [ROWS * (NH * CV)];
__device__ float g_p1  [ROWS * HID];
__device__ float g_wq  [QKVG_N * HID];
__device__ float g_bq  [QKVG_N];

// ---------------- helpers ----------------
__device__ __forceinline__ float sigmoidf_(float x) { return 1.0f / (1.0f + expf(-x)); }

// split (x,y) into packed fp16 hi pair + fp16 lo pair (2xFP16 decomposition).
// low 16 bits of each word = x (even k), high = y (odd k).
__device__ __forceinline__ void h2pair(float x, float y, uint32_t& hi, uint32_t& lo) {
    __half hx = __float2half_rn(x), hy = __float2half_rn(y);
    float rx = x - __half2float(hx), ry = y - __half2float(hy);
    __half2 H = __halves2half2(hx, hy);
    __half2 L = __halves2half2(__float2half_rn(rx), __float2half_rn(ry));
    hi = *reinterpret_cast<uint32_t*>(&H);
    lo = *reinterpret_cast<uint32_t*>(&L);
}

__device__ __forceinline__ void mma_f16(float* c, const uint32_t* a, const uint32_t* b) {
    asm volatile(
        "mma.sync.aligned.m16n8k16.row.col.f32.f16.f16.f32 "
        "{%0,%1,%2,%3}, {%4,%5,%6,%7}, {%8,%9}, {%0,%1,%2,%3};"
        : "+f"(c[0]), "+f"(c[1]), "+f"(c[2]), "+f"(c[3])
        : "r"(a[0]), "r"(a[1]), "r"(a[2]), "r"(a[3]), "r"(b[0]), "r"(b[1]));
}

// ---------------- 2xFP16 (3-term) mma.sync GEMM ----------------
// C[M,N] = A[M,K] @ B[N,K]^T + bias, fp32-accurate: a=ah+al, b=bh+bl (fp16 each),
// C = ah*bh + ah*bl + al*bh  (dropped al*bl ~ 2^-22).
// Split-A source: k < K1 from A1 (lda1) else A2 at k-K1 (lda2). K1 % 16 == 0, K % 16 == 0.
// CTA tile 128x128, K-chunk 16 (one m16n8k16 k-step), 256 threads (8 warps = 2m x 4n),
// warp tile 64x32. Smem per stage (u32 words): A_hi[1024] A_lo[1024] B_hi[1024] B_lo[1024]
// = 16KB; double-buffered 32KB. __launch_bounds__(256,2) -> 2 CTAs/SM.
// Fragment word layout (conflict-free vector LDS):
//   A: [mf(8)][lane(32)][reg(4)]  reg = khalf*2 + rhi ; lane = gid*4 + tig
//   B: [nf(16)][lane(32)][reg(2)] reg = khalf        ; lane = gid*4 + tig
#define TG_SMEM 32768

__global__ __launch_bounds__(256, 2) void tgemm_h2(
    const float* __restrict__ A1, const float* __restrict__ A2,
    int K1, int lda1, int lda2,
    const float* __restrict__ B, const float* __restrict__ bias,
    float* __restrict__ C, int ldc, int N, int K, int mode)
{
    extern __shared__ float smf[];
    uint32_t* smw = (uint32_t*)smf;

    const int tid = threadIdx.x;
    const int lane = tid & 31;
    const int wid = tid >> 5;
    const int wm = wid & 1;          // m offset wm*64
    const int wn = wid >> 1;         // n offset wn*32
    const int m0 = blockIdx.y * 128;
    const int n0 = blockIdx.x * 128;

    // per-thread staging coords (two passes r=0,1 over e = tid + r*256)
    int rowv[2], kqv[2], offA[2], offB[2];
#pragma unroll
    for (int r = 0; r < 2; r++) {
        int e = tid + r * 256;
        int row = e >> 2;            // 0..127
        int kq = (e & 3) * 4;        // 0,4,8,12
        rowv[r] = row; kqv[r] = kq;
        int mf = row >> 4, rr = row & 15, gid = rr & 7, rhi = rr >> 3;
        int khalf = kq >> 3, tig0 = (kq >> 1) & 3;
        offA[r] = mf * 128 + (gid * 4 + tig0) * 4 + khalf * 2 + rhi;
        int nf = row >> 3, gidB = row & 7;
        offB[r] = nf * 64 + (gidB * 4 + tig0) * 2 + khalf;
    }

    float acc[4][4][4];
#pragma unroll
    for (int i = 0; i < 4; i++)
#pragma unroll
        for (int j = 0; j < 4; j++)
#pragma unroll
            for (int r = 0; r < 4; r++) acc[i][j][r] = 0.f;

    const int nch = K / 16;

    float4 fA[2], fB[2];
    auto ldg = [&](int c) {
#pragma unroll
        for (int r = 0; r < 2; r++) {
            int kg = c * 16 + kqv[r];
            int row = rowv[r];
            const float* pA = (kg < K1) ? A1 + (size_t)(m0 + row) * lda1 + kg
                                        : A2 + (size_t)(m0 + row) * lda2 + (kg - K1);
            fA[r] = *(const float4*)pA;
            fB[r] = make_float4(0.f, 0.f, 0.f, 0.f);
            if (n0 + row < N) fB[r] = *(const float4*)(B + (size_t)(n0 + row) * K + kg);
        }
    };
    auto store = [&](int buf) {
        uint32_t* s = smw + buf * 4096;
#pragma unroll
        for (int r = 0; r < 2; r++) {
            uint32_t h0, l0, h1, l1;
            h2pair(fA[r].x, fA[r].y, h0, l0);
            h2pair(fA[r].z, fA[r].w, h1, l1);
            s[offA[r]]            = h0; s[1024 + offA[r]]     = l0;
            s[offA[r] + 4]        = h1; s[1024 + offA[r] + 4] = l1;
            h2pair(fB[r].x, fB[r].y, h0, l0);
            h2pair(fB[r].z, fB[r].w, h1, l1);
            s[2048 + offB[r]]     = h0; s[3072 + offB[r]]     = l0;
            s[2048 + offB[r] + 2] = h1; s[3072 + offB[r] + 2] = l1;
        }
    };

    ldg(0);
    store(0);
    __syncthreads();

    for (int c = 0; c < nch; c++) {
        if (c + 1 < nch) ldg(c + 1);

        // ---- compute chunk c ----
        const uint32_t* sw = smw + (c & 1) * 4096;
        uint32_t bh[4][2], bl[4][2];
#pragma unroll
        for (int j = 0; j < 4; j++) {
            const int nf = wn * 4 + j;
            uint2 vh = *(const uint2*)(sw + 2048 + nf * 64 + lane * 2);
            uint2 vl = *(const uint2*)(sw + 3072 + nf * 64 + lane * 2);
            bh[j][0] = vh.x; bh[j][1] = vh.y;
            bl[j][0] = vl.x; bl[j][1] = vl.y;
        }
#pragma unroll
        for (int i = 0; i < 4; i++) {
            const int mf = wm * 4 + i;
            uint4 vh = *(const uint4*)(sw + mf * 128 + lane * 4);
            uint4 vl = *(const uint4*)(sw + 1024 + mf * 128 + lane * 4);
            uint32_t ah[4] = {vh.x, vh.y, vh.z, vh.w};
            uint32_t al[4] = {vl.x, vl.y, vl.z, vl.w};
#pragma unroll
            for (int j = 0; j < 4; j++) {
                mma_f16(acc[i][j], al, bh[j]);   // lo*hi
                mma_f16(acc[i][j], ah, bl[j]);   // hi*lo
                mma_f16(acc[i][j], ah, bh[j]);   // hi*hi
            }
        }

        if (c + 1 < nch) store((c + 1) & 1);
        __syncthreads();
    }

    // ---- epilogue ----
    const int gid = lane >> 2;
    const int tig = lane & 3;
#pragma unroll
    for (int i = 0; i < 4; i++) {
        const int row0 = m0 + wm * 64 + i * 16 + gid;
#pragma unroll
        for (int j = 0; j < 4; j++) {
            const int col = n0 + wn * 32 + j * 8 + tig * 2;
            if (col < N) {
                float b0 = bias[col], b1 = bias[col + 1];
                float v0 = acc[i][j][0] + b0, v1 = acc[i][j][1] + b1;
                float v2 = acc[i][j][2] + b0, v3 = acc[i][j][3] + b1;
                if (mode == M_RELU) {
                    v0 = fmaxf(v0, 0.f); v1 = fmaxf(v1, 0.f);
                    v2 = fmaxf(v2, 0.f); v3 = fmaxf(v3, 0.f);
                } else if (mode == M_QKVG && col >= 192) {
                    v0 = sigmoidf_(v0); v1 = sigmoidf_(v1);
                    v2 = sigmoidf_(v2); v3 = sigmoidf_(v3);
                }
                *(float2*)(C + (size_t)row0 * ldc + col)       = make_float2(v0, v1);
                *(float2*)(C + (size_t)(row0 + 8) * ldc + col) = make_float2(v2, v3);
            }
        }
    }
}

// ---------------- SIMT f32x2 GEMM (p2, N=20) ----------------
__device__ __forceinline__ ull pk2(float x) {
    ull r; asm("mov.b64 %0, {%1, %1};" : "=l"(r) : "f"(x)); return r;
}
__device__ __forceinline__ ull pk(float x, float y) {
    ull r; asm("mov.b64 %0, {%1, %2};" : "=l"(r) : "f"(x), "f"(y)); return r;
}
__device__ __forceinline__ void fma2(ull& d, ull a, ull b) {
    asm("fma.rn.f32x2 %0, %1, %2, %0;" : "+l"(d) : "l"(a), "l"(b));
}
__device__ __forceinline__ void unpk(ull v, float& x, float& y) {
    asm("mov.b64 {%0, %1}, %2;" : "=f"(x), "=f"(y) : "l"(v));
}

#define BM 128
#define BK 16
template<int BN>
__global__ __launch_bounds__(256, 2) void gemm8x8(
    const float* __restrict__ A1, const float* __restrict__ B, const float* __restrict__ bias,
    float* __restrict__ C, int ldc, int N, int K, int lda)
{
    constexpr int TN  = BN / 16;
    constexpr int PAD = 4;
    __shared__ __align__(16) float As[BK][BM + PAD];
    __shared__ __align__(16) float Bs[BK][BN + PAD];

    const int tid = threadIdx.x;
    const int m0 = blockIdx.y * BM;
    const int n0 = blockIdx.x * BN;
    const int tx = tid & 15;
    const int ty = tid >> 4;

    ull acc[8][TN / 2];
#pragma unroll
    for (int i = 0; i < 8; i++)
#pragma unroll
        for (int p = 0; p < TN / 2; p++) acc[i][p] = 0ull;

    for (int k0 = 0; k0 < K; k0 += BK) {
#pragma unroll
        for (int r = 0; r < 2; r++) {
            int e = tid + r * 256;
            int row = e >> 2;
            int kq = (e & 3) * 4;
            float4 v = *(const float4*)(A1 + (size_t)(m0 + row) * lda + k0 + kq);
            As[kq + 0][row] = v.x; As[kq + 1][row] = v.y;
            As[kq + 2][row] = v.z; As[kq + 3][row] = v.w;
        }
#pragma unroll
        for (int r = 0; r < BN / 64; r++) {
            int e = tid + r * 256;
            int col = e >> 2;
            int kq = (e & 3) * 4;
            float4 v = make_float4(0.f, 0.f, 0.f, 0.f);
            if (n0 + col < N) v = *(const float4*)(B + (size_t)(n0 + col) * K + k0 + kq);
            Bs[kq + 0][col] = v.x; Bs[kq + 1][col] = v.y;
            Bs[kq + 2][col] = v.z; Bs[kq + 3][col] = v.w;
        }
        __syncthreads();

#pragma unroll
        for (int kk = 0; kk < BK; kk++) {
            float4 a0 = *(const float4*)&As[kk][ty * 8];
            float4 a1 = *(const float4*)&As[kk][ty * 8 + 4];
            float am[8] = {a0.x, a0.y, a0.z, a0.w, a1.x, a1.y, a1.z, a1.w};
            float bn_[TN];
#pragma unroll
            for (int q = 0; q < TN / 4; q++) {
                float4 b = *(const float4*)&Bs[kk][tx * TN + q * 4];
                bn_[q * 4 + 0] = b.x; bn_[q * 4 + 1] = b.y;
                bn_[q * 4 + 2] = b.z; bn_[q * 4 + 3] = b.w;
            }
            ull bp[TN / 2];
#pragma unroll
            for (int p = 0; p < TN / 2; p++) bp[p] = pk(bn_[2 * p], bn_[2 * p + 1]);
#pragma unroll
            for (int i = 0; i < 8; i++) {
                ull aa = pk2(am[i]);
#pragma unroll
                for (int p = 0; p < TN / 2; p++) fma2(acc[i][p], aa, bp[p]);
            }
        }
        __syncthreads();
    }

#pragma unroll
    for (int i = 0; i < 8; i++) {
        int row = m0 + ty * 8 + i;
        float vals[TN];
#pragma unroll
        for (int p = 0; p < TN / 2; p++) unpk(acc[i][p], vals[2 * p], vals[2 * p + 1]);
#pragma unroll
        for (int j = 0; j < TN; j++) {
            int col = n0 + tx * TN + j;
            if (col < N) C[(size_t)row * ldc + col] = vals[j] + bias[col];
        }
    }
}

// ---------------- pack q/k/v/g ----------------
__global__ void pack_qkvg(const float* __restrict__ qw, const float* __restrict__ qb,
                          const float* __restrict__ kw, const float* __restrict__ kb,
                          const float* __restrict__ vw, const float* __restrict__ vb,
                          const float* __restrict__ gw, const float* __restrict__ gb)
{
    int i = blockIdx.x * blockDim.x + threadIdx.x;
    const int total = QKVG_N * HID;
    if (i < total) {
        int row = i / HID, c = i - row * HID;
        float v;
        if      (row < 64)  v = qw[row * HID + c];
        else if (row < 128) v = kw[(row - 64) * HID + c];
        else if (row < 192) v = vw[(row - 128) * HID + c];
        else                v = gw[(row - 192) * HID + c];
        g_wq[i] = v;
    }
    if (i < QKVG_N) {
        float b;
        if      (i < 64)  b = qb[i];
        else if (i < 128) b = kb[i - 64];
        else if (i < 192) b = vb[i - 128];
        else              b = gb[i - 192];
        g_bq[i] = b;
    }
}

// ---------------- GRU gate fusion ----------------
__global__ void gru_gates(const float* __restrict__ gi, const float* __restrict__ gh,
                          const float* __restrict__ hin, float* __restrict__ hout)
{
    int i4 = blockIdx.x * blockDim.x + threadIdx.x;
    if (i4 >= ROWS * (HID / 4)) return;
    int row = i4 >> 6;
    int c   = (i4 & 63) << 2;
    const float* gib = gi + (size_t)row * 768 + c;
    const float* ghb = gh + (size_t)row * 768 + c;
    float4 gir = *(const float4*)(gib);
    float4 giz = *(const float4*)(gib + 256);
    float4 gin = *(const float4*)(gib + 512);
    float4 ghr = *(const float4*)(ghb);
    float4 ghz = *(const float4*)(ghb + 256);
    float4 ghn = *(const float4*)(ghb + 512);
    float4 h0  = *(const float4*)(hin + (size_t)row * HID + c);
    float4 o;
    {
        float r = sigmoidf_(gir.x + ghr.x);
        float z = sigmoidf_(giz.x + ghz.x);
        float n = tanhf(gin.x + r * ghn.x);
        o.x = (1.f - z) * n + z * h0.x;
    }
    {
        float r = sigmoidf_(gir.y + ghr.y);
        float z = sigmoidf_(giz.y + ghz.y);
        float n = tanhf(gin.y + r * ghn.y);
        o.y = (1.f - z) * n + z * h0.y;
    }
    {
        float r = sigmoidf_(gir.z + ghr.z);
        float z = sigmoidf_(giz.z + ghz.z);
        float n = tanhf(gin.z + r * ghn.z);
        o.z = (1.f - z) * n + z * h0.z;
    }
    {
        float r = sigmoidf_(gir.w + ghr.w);
        float z = sigmoidf_(giz.w + ghz.w);
        float n = tanhf(gin.w + r * ghn.w);
        o.w = (1.f - z) * n + z * h0.w;
    }
    *(float4*)(hout + (size_t)row * HID + c) = o;
}

// ---------------- per-batch sparse attention ----------------
__global__ __launch_bounds__(128) void attention_kernel(const float* __restrict__ qkvg,
                                                        float* __restrict__ msg)
{
    __shared__ float q_s[A_][64];
    __shared__ float k_s[A_][64];
    __shared__ float v_s[A_][64];
    __shared__ float g_s[A_][NH];

    const int b = blockIdx.x;
    const int tid = threadIdx.x;
    const float* base = qkvg + (size_t)b * A_ * QKVG_N;

    for (int idx = tid; idx < A_ * QKVG_N; idx += 128) {
        int r = idx / QKVG_N, c = idx - r * QKVG_N;
        float v = base[(size_t)r * QKVG_N + c];
        if      (c < 64)  q_s[r][c] = v;
        else if (c < 128) k_s[r][c - 64] = v;
        else if (c < 192) v_s[r][c - 128] = v;
        else              g_s[r][c - 192] = v;
    }
    __syncthreads();

    const int qa = tid >> 2;
    const int hh = tid & 3;
    const int hb = hh * HD;

    float qv[HD];
#pragma unroll
    for (int d = 0; d < HD; d++) qv[d] = q_s[qa][hb + d];

    float sc[A_];
#pragma unroll
    for (int ka = 0; ka < A_; ka++) {
        float s = 0.f;
#pragma unroll
        for (int d = 0; d < HD; d++) s += qv[d] * k_s[ka][hb + d];
        sc[ka] = (ka == qa) ? NEGV : s * 0.25f;
    }

    unsigned sel = 0;
    float maxv = NEGV;
    for (int it = 0; it < TOPK; it++) {
        float best = -INFINITY; int bi = 0;
#pragma unroll
        for (int ka = 0; ka < A_; ka++) {
            bool free_ = !((sel >> ka) & 1u);
            if (free_ && sc[ka] > best) { best = sc[ka]; bi = ka; }
        }
        sel |= (1u << bi);
        if (it == 0) maxv = best;
    }

    float sum = 0.f;
#pragma unroll
    for (int ka = 0; ka < A_; ka++) {
        float e = ((sel >> ka) & 1u) ? expf(sc[ka] - maxv) : 0.f;
        sc[ka] = e;
        sum += e;
    }
    float inv = 1.f / sum;

    float m[CV];
#pragma unroll
    for (int d = 0; d < CV; d++) m[d] = 0.f;
#pragma unroll
    for (int ka = 0; ka < A_; ka++) {
        float w = sc[ka];
#pragma unroll
        for (int d = 0; d < CV; d++) m[d] += w * v_s[ka][hb + d];
    }

    float gate = g_s[qa][hh];
    float* out = msg + ((size_t)(b * A_ + qa)) * (NH * CV) + hb;
#pragma unroll
    for (int d = 0; d < CV; d++) out[d] = m[d] * inv * gate;
}

// ---------------- launch ----------------
extern "C" void kernel_launch(void* const* d_in, const int* in_sizes, int n_in,
                              void* d_out, int out_size)
{
    const float* inputs = (const float*)d_in[0];
    const float* hidden = (const float*)d_in[1];
    const float* fc1_w  = (const float*)d_in[2];
    const float* fc1_b  = (const float*)d_in[3];
    const float* w_ih   = (const float*)d_in[4];
    const float* w_hh   = (const float*)d_in[5];
    const float* b_ih   = (const float*)d_in[6];
    const float* b_hh   = (const float*)d_in[7];
    const float* q_w    = (const float*)d_in[8];
    const float* q_b    = (const float*)d_in[9];
    const float* k_w    = (const float*)d_in[10];
    const float* k_b    = (const float*)d_in[11];
    const float* v_w    = (const float*)d_in[12];
    const float* v_b    = (const float*)d_in[13];
    const float* g_w    = (const float*)d_in[14];
    const float* g_b    = (const float*)d_in[15];
    const float* p1_w   = (const float*)d_in[16];
    const float* p1_b   = (const float*)d_in[17];
    const float* p2_w   = (const float*)d_in[18];
    const float* p2_b   = (const float*)d_in[19];

    float* out    = (float*)d_out;
    float* logits = out;                       // [65536, 20]
    float* hout   = out + (size_t)ROWS * NACT; // [65536, 256]

    float *x, *gi, *gh, *qkvg, *msg, *p1, *wq, *bq;
    cudaGetSymbolAddress((void**)&x,    g_x);
    cudaGetSymbolAddress((void**)&gi,   g_gi);
    cudaGetSymbolAddress((void**)&gh,   g_gh);
    cudaGetSymbolAddress((void**)&qkvg, g_qkvg);
    cudaGetSymbolAddress((void**)&msg,  g_msg);
    cudaGetSymbolAddress((void**)&p1,   g_p1);
    cudaGetSymbolAddress((void**)&wq,   g_wq);
    cudaGetSymbolAddress((void**)&bq,   g_bq);

    const int MYT = ROWS / 128;   // 512

    pack_qkvg<<<(QKVG_N * HID + 255) / 256, 256>>>(q_w, q_b, k_w, k_b, v_w, v_b, g_w, g_b);

    // x = relu(inputs @ fc1_w^T + fc1_b)
    tgemm_h2<<<dim3(HID / 128, MYT), 256, TG_SMEM>>>(
        inputs, inputs, IN_DIM, IN_DIM, IN_DIM, fc1_w, fc1_b, x, HID, HID, IN_DIM, M_RELU);
    // gi = x @ w_ih^T + b_ih ; gh = hidden @ w_hh^T + b_hh
    tgemm_h2<<<dim3(3 * HID / 128, MYT), 256, TG_SMEM>>>(
        x, x, HID, HID, HID, w_ih, b_ih, gi, 3 * HID, 3 * HID, HID, M_NONE);
    tgemm_h2<<<dim3(3 * HID / 128, MYT), 256, TG_SMEM>>>(
        hidden, hidden, HID, HID, HID, w_hh, b_hh, gh, 3 * HID, 3 * HID, HID, M_NONE);
    // h
    gru_gates<<<(ROWS * (HID / 4) + 255) / 256, 256>>>(gi, gh, hidden, hout);
    // q|k|v|sig(g)
    tgemm_h2<<<dim3((QKVG_N + 127) / 128, MYT), 256, TG_SMEM>>>(
        hout, hout, HID, HID, HID, wq, bq, qkvg, QKVG_N, QKVG_N, HID, M_QKVG);
    // sparse attention -> gated messages
    attention_kernel<<<BS_, 128>>>(qkvg, msg);
    // p1 = relu([h | msg] @ p1_w^T + p1_b)   (split-A, K=320)
    tgemm_h2<<<dim3(HID / 128, MYT), 256, TG_SMEM>>>(
        hout, msg, HID, HID, NH * CV, p1_w, p1_b, p1, HID, HID, HID + NH * CV, M_RELU);
    // logits = p1 @ p2_w^T + p2_b  (SIMT fp32, N=20)
    gemm8x8<64><<<dim3(1, ROWS / BM), 256>>>(p1, p2_w, p2_b, logits, NACT, NACT, HID, HID);
}